// round 17
// baseline (speedup 1.0000x reference)
#include <cuda_runtime.h>
#include <cfloat>
#include <stdint.h>

// x [64,256,32,32] f32, codebook [1024,256] f32
#define D_DIM   256
#define HW_DIM  1024
#define NPIX    65536
#define KCODE   1024
#define TOT_ELEMS 16777216

typedef unsigned long long u64;

// Scratch (device globals; allocation-free)
__device__ float  g_cn[KCODE];
__device__ float  g_xn[NPIX];
__device__ u64    g_key[NPIX];      // (d2_bits<<32)|code, atomicMin-merged
__device__ double g_partial[512];

// ===================== packed f32x2 helpers (sm_100+) =====================
__device__ __forceinline__ u64 fma2(u64 a, u64 b, u64 c) {
    u64 d;
    asm("fma.rn.f32x2 %0, %1, %2, %3;" : "=l"(d) : "l"(a), "l"(b), "l"(c));
    return d;
}
__device__ __forceinline__ u64 dup2(float v) {
    u64 d;
    asm("mov.b64 %0, {%1, %1};" : "=l"(d) : "f"(v));
    return d;
}
__device__ __forceinline__ float lo2(u64 v) {
    float l, h;
    asm("mov.b64 {%0, %1}, %2;" : "=f"(l), "=f"(h) : "l"(v));
    return l;
}
__device__ __forceinline__ float hi2(u64 v) {
    float l, h;
    asm("mov.b64 {%0, %1}, %2;" : "=f"(l), "=f"(h) : "l"(v));
    return h;
}

// B smem column swizzle (round-9 validated): code c at word c + 4*(c>>5);
// 8-lane LDS.128 phases cover all 32 banks. Row pitch 140 words.
#define BPITCH 140
__device__ __forceinline__ int bcol(int c) { return c + 4 * (c >> 5); }

// ---------------------------------------------------------------------------
// norms (scalar-sequential order — bit-exact-validated in round 2)
// ---------------------------------------------------------------------------
__global__ void cnorm_kernel(const float* __restrict__ cb) {
    int k = blockIdx.x * 256 + threadIdx.x;
    const float* row = cb + (size_t)k * D_DIM;
    float s = 0.f;
    for (int d = 0; d < D_DIM; d++) s = __fadd_rn(s, __fmul_rn(row[d], row[d]));
    g_cn[k] = s;
}
__global__ void xnorm_kernel(const float* __restrict__ x) {
    int b = blockIdx.x, t = threadIdx.x;
    const float* xb = x + (size_t)b * D_DIM * HW_DIM + t * 4;
    float sa[4] = {0.f, 0.f, 0.f, 0.f};
    for (int d = 0; d < D_DIM; d++) {
        float4 v = *(const float4*)(xb + (size_t)d * HW_DIM);
        sa[0] = __fadd_rn(sa[0], __fmul_rn(v.x, v.x));
        sa[1] = __fadd_rn(sa[1], __fmul_rn(v.y, v.y));
        sa[2] = __fadd_rn(sa[2], __fmul_rn(v.z, v.z));
        sa[3] = __fadd_rn(sa[3], __fmul_rn(v.w, v.w));
    }
    int p = b * HW_DIM + t * 4;
#pragma unroll
    for (int j = 0; j < 4; j++) {
        g_xn[p + j]  = sa[j];
        g_key[p + j] = ~0ull;
    }
}

// ---------------------------------------------------------------------------
// Main VQ (round-16, unchanged): round-13 FFMA2 core, 256-code quarter per
// CTA, 2048 jobs -> 98.9% packing, u64 atomicMin merge. Bit-exact chain.
// ---------------------------------------------------------------------------
__global__ __launch_bounds__(256, 2)
void vq_kernel(const float* __restrict__ x,
               const float* __restrict__ cb) {
    __shared__ __align__(16) float As[2][16][128];
    __shared__ __align__(16) float Bs[2][16][BPITCH];
    __shared__ float cns[KCODE];
    __shared__ float xns[128];
    __shared__ float bestv[128];
    __shared__ int   besti[128];

    const int t  = threadIdx.x;
    const int tx = t & 15;
    const int ty = t >> 4;
    const int pb = blockIdx.x & 511;
    const int qq = blockIdx.x >> 9;
    const int p0   = pb * 128;
    const int bimg = p0 >> 10;
    const int hwb  = p0 & 1023;
    const int code0 = qq * 256;
    const float* xb = x + (size_t)bimg * D_DIM * HW_DIM + hwb;

#pragma unroll
    for (int i = 0; i < 4; i++) cns[t + i * 256] = g_cn[t + i * 256];
    if (t < 128) {
        xns[t] = g_xn[p0 + t];
        bestv[t] = FLT_MAX; besti[t] = 0x7fffffff;
    }

    const int dkA0 = t >> 5, dkA1 = dkA0 + 8;
    const int ppA  = (t & 31) * 4;
    const int cc0  = t >> 2, cc1 = cc0 + 64;
    const int ds0  = (t & 3) * 4;
    const int col0 = bcol(cc0), col1 = bcol(cc1);
    const int rcol = tx * 8 + 4 * (tx >> 2);

    u64 acc2[8][4];
    float4 ra0, ra1, rb0, rb1;
    ra0 = *(const float4*)(xb + (size_t)dkA0 * HW_DIM + ppA);
    ra1 = *(const float4*)(xb + (size_t)dkA1 * HW_DIM + ppA);
    rb0 = *(const float4*)(cb + (size_t)(code0 + cc0) * D_DIM + ds0);
    rb1 = *(const float4*)(cb + (size_t)(code0 + cc1) * D_DIM + ds0);

    for (int it = 0; it < 32; it++) {
        const int nc = it >> 4, kc = it & 15, buf = it & 1;

        *(float4*)&As[buf][dkA0][ppA] = ra0;
        *(float4*)&As[buf][dkA1][ppA] = ra1;
        Bs[buf][ds0 + 0][col0] = rb0.x; Bs[buf][ds0 + 1][col0] = rb0.y;
        Bs[buf][ds0 + 2][col0] = rb0.z; Bs[buf][ds0 + 3][col0] = rb0.w;
        Bs[buf][ds0 + 0][col1] = rb1.x; Bs[buf][ds0 + 1][col1] = rb1.y;
        Bs[buf][ds0 + 2][col1] = rb1.z; Bs[buf][ds0 + 3][col1] = rb1.w;
        __syncthreads();

        if (it < 31) {
            const int kn = (it + 1) & 15, nn = (it + 1) >> 4;
            ra0 = *(const float4*)(xb + (size_t)(kn * 16 + dkA0) * HW_DIM + ppA);
            ra1 = *(const float4*)(xb + (size_t)(kn * 16 + dkA1) * HW_DIM + ppA);
            rb0 = *(const float4*)(cb + (size_t)(code0 + nn * 128 + cc0) * D_DIM + kn * 16 + ds0);
            rb1 = *(const float4*)(cb + (size_t)(code0 + nn * 128 + cc1) * D_DIM + kn * 16 + ds0);
        }

        if (kc == 0) {
#pragma unroll
            for (int i = 0; i < 8; i++)
#pragma unroll
                for (int j = 0; j < 4; j++) acc2[i][j] = 0ull;
        }

#pragma unroll
        for (int dk = 0; dk < 16; dk++) {
            float4 af0 = *(const float4*)&As[buf][dk][ty * 8];
            float4 af1 = *(const float4*)&As[buf][dk][ty * 8 + 4];
            ulonglong2 bq0 = *(const ulonglong2*)&Bs[buf][dk][rcol];
            ulonglong2 bq1 = *(const ulonglong2*)&Bs[buf][dk][rcol + 4];
            u64 bp[4] = {bq0.x, bq0.y, bq1.x, bq1.y};
            float av[8] = {af0.x, af0.y, af0.z, af0.w,
                           af1.x, af1.y, af1.z, af1.w};
#pragma unroll
            for (int i = 0; i < 8; i++) {
                u64 ad = dup2(av[i]);
#pragma unroll
                for (int jp = 0; jp < 4; jp++)
                    acc2[i][jp] = fma2(ad, bp[jp], acc2[i][jp]);
            }
        }

        if (kc == 15) {
            const int cbase = code0 + nc * 128;
#pragma unroll
            for (int i = 0; i < 8; i++) {
                const int r = ty * 8 + i;
                const float xn = xns[r];
                float bv = FLT_MAX;
                int   bi = 0x7fffffff;
#pragma unroll
                for (int jp = 0; jp < 4; jp++) {
                    const int c0 = cbase + tx * 8 + 2 * jp;
                    float vlo = lo2(acc2[i][jp]);
                    float vhi = hi2(acc2[i][jp]);
                    float d0 = __fadd_rn(__fadd_rn(xn, __fmul_rn(-2.f, vlo)), cns[c0]);
                    float d1 = __fadd_rn(__fadd_rn(xn, __fmul_rn(-2.f, vhi)), cns[c0 + 1]);
                    if (d0 < bv) { bv = d0; bi = c0; }
                    if (d1 < bv) { bv = d1; bi = c0 + 1; }
                }
#pragma unroll
                for (int off = 8; off > 0; off >>= 1) {
                    float ov = __shfl_down_sync(0xffffffffu, bv, off, 16);
                    int   oi = __shfl_down_sync(0xffffffffu, bi, off, 16);
                    if (ov < bv || (ov == bv && oi < bi)) { bv = ov; bi = oi; }
                }
                if (tx == 0) {
                    if (bv < bestv[r] || (bv == bestv[r] && bi < besti[r])) {
                        bestv[r] = bv; besti[r] = bi;
                    }
                }
            }
        }
    }
    __syncthreads();

    if (t < 128) {
        u64 key = ((u64)__float_as_uint(bestv[t]) << 32) | (unsigned)besti[t];
        atomicMin(&g_key[p0 + t], key);
    }
}

// ---------------------------------------------------------------------------
// Output: smem-staged codebook gather (coalesced LDG, conflict-free LDS),
// STE rounding + loss partial. Math bit-identical to the validated chain.
// ---------------------------------------------------------------------------
#define QPITCH 257
__global__ __launch_bounds__(256)
void output_kernel(const float* __restrict__ x, const float* __restrict__ cb,
                   float* __restrict__ out) {
    __shared__ float qtile[32 * QPITCH];   // 32 code rows, stride 257 words
    __shared__ int besti[128];
    __shared__ double red[256];
    const int t = threadIdx.x, lane = t & 31, wd = t >> 5;
    const int p0 = blockIdx.x * 128, bimg = p0 >> 10, hwb = p0 & 1023;
    if (t < 128) besti[t] = (int)(unsigned)(g_key[p0 + t] & 0xffffffffull);

    double lsum = 0.0;
    const int pp = t & 31;        // emission: lane -> pixel (coalesced)
    const int dh = t >> 5;        // warp -> d sub-offset

    for (int c = 0; c < 4; c++) {
        __syncthreads();          // qtile free (prev chunk fully read)
        // stage 32 code rows: warp wd loads rows wd, wd+8, wd+16, wd+24
#pragma unroll
        for (int rr = 0; rr < 4; rr++) {
            const int r = wd + rr * 8;
            const float4* src = (const float4*)(cb + (size_t)besti[c * 32 + r] * D_DIM);
#pragma unroll
            for (int i = 0; i < 2; i++) {
                float4 v = src[lane + 32 * i];      // coalesced 128B
                float* q = qtile + r * QPITCH + (lane + 32 * i) * 4;
                q[0] = v.x; q[1] = v.y; q[2] = v.z; q[3] = v.w;   // banks r+i: CF
            }
        }
        __syncthreads();

        // emit 32 px x 256 d: LDS bank = pp+d (CF), LDG/STG 128B coalesced
#pragma unroll 4
        for (int m = 0; m < 32; m++) {
            const int d = m * 8 + dh;
            size_t addr = (size_t)(bimg * D_DIM + d) * HW_DIM + hwb + c * 32 + pp;
            float q  = qtile[pp * QPITCH + d];
            float xv = x[addr];
            out[addr] = __fadd_rn(xv, __fsub_rn(q, xv));
            float diff = __fsub_rn(xv, q);
            lsum += (double)__fmul_rn(diff, diff);
        }
    }

    red[t] = lsum;
    __syncthreads();
    for (int s = 128; s > 0; s >>= 1) {
        if (t < s) red[t] += red[t + s];
        __syncthreads();
    }
    if (t == 0) g_partial[blockIdx.x] = red[0];
}

// ---------------------------------------------------------------------------
__global__ void finalize_kernel(float* __restrict__ out, int out_size) {
    __shared__ double red[512];
    int t = threadIdx.x;
    red[t] = g_partial[t];
    __syncthreads();
    for (int s = 256; s > 0; s >>= 1) {
        if (t < s) red[t] += red[t + s];
        __syncthreads();
    }
    if (t == 0) {
        float m = (float)(red[0] / (double)TOT_ELEMS);
        float loss = (float)(1.25 * (double)m);
        for (int i = TOT_ELEMS; i < out_size; i++) out[i] = loss;
    }
}

// ---------------------------------------------------------------------------
extern "C" void kernel_launch(void* const* d_in, const int* in_sizes, int n_in,
                              void* d_out, int out_size) {
    const float* x  = (const float*)d_in[0];
    const float* cb = (const float*)d_in[1];
    float* out = (float*)d_out;

    cnorm_kernel<<<KCODE / 256, 256>>>(cb);
    xnorm_kernel<<<64, 256>>>(x);
    vq_kernel<<<2048, 256>>>(x, cb);
    output_kernel<<<NPIX / 128, 256>>>(x, cb, out);
    finalize_kernel<<<1, 512>>>(out, out_size);
}